// round 11
// baseline (speedup 1.0000x reference)
#include <cuda_runtime.h>

// out[b, r, c] = x[b, r, c] * weight[c], N = 4096 (power of two)
// Memory-roofline stream (~7.2 TB/s effective, ~90% of HBM3e spec).
// 8x float4/thread front-batched (MLP=8), block chunk = 2048 float4 = two
// 4096-col rows -> weight columns thread-invariant with period 4 (wv[k&3]).
// Streaming hints on x/out, exact grid cover, 32-bit indexing.

#define THREADS 256
#define UNROLL  8
// block chunk = 2048 float4 = 8192 scalars = exactly two weight rows

__global__ void __launch_bounds__(THREADS) scale_lastdim_u8_kernel(
    const float4* __restrict__ x4,
    const float*  __restrict__ w,
    float4* __restrict__ out4)
{
    const unsigned t = threadIdx.x;
    const unsigned base = blockIdx.x * (THREADS * UNROLL) + t;

    // (global_col & 4095) == t*4 + (k&3)*1024 : period-4 in k
    float4 wv[4];
#pragma unroll
    for (int k = 0; k < 4; k++)
        wv[k] = __ldg((const float4*)(w + k * 1024 + t * 4));  // 16 KB, L1-hit

    // Front-batch 8 independent LDG.128 (streaming: x never reused)
    float4 xv[UNROLL];
#pragma unroll
    for (int k = 0; k < UNROLL; k++)
        xv[k] = __ldcs(&x4[base + k * THREADS]);

#pragma unroll
    for (int k = 0; k < UNROLL; k++) {
        const float4 wk = wv[k & 3];
        float4 ov;
        ov.x = xv[k].x * wk.x;
        ov.y = xv[k].y * wk.y;
        ov.z = xv[k].z * wk.z;
        ov.w = xv[k].w * wk.w;
        __stcs(&out4[base + k * THREADS], ov);
    }
}

extern "C" void kernel_launch(void* const* d_in, const int* in_sizes, int n_in,
                              void* d_out, int out_size)
{
    const float* x = (const float*)d_in[0];
    const float* w = (const float*)d_in[1];
    float* out = (float*)d_out;

    long long n  = (long long)out_size;         // 4*4096*4096 = 67108864
    unsigned n4 = (unsigned)(n >> 2);           // 16777216 float4s
    unsigned blocks = n4 / (THREADS * UNROLL);  // 8192, exact cover

    scale_lastdim_u8_kernel<<<blocks, THREADS>>>(
        (const float4*)x, w, (float4*)out);
}